// round 11
// baseline (speedup 1.0000x reference)
#include <cuda_runtime.h>
#include <cuda_bf16.h>
#include <math.h>

// Problem constants
#define B_   2
#define S_   2048
#define D_   2048
#define NH_  16
#define HD_  128
#define M_   (B_*S_)          // 4096 total rows
#define KC_N (D_/16)          // 128 k16-chunks per row
#define NK_  (D_/32)          // 64 k-iterations of BK=32

// ---------------------------------------------------------------------------
// Scratch (static device globals — no runtime allocation allowed)
// ---------------------------------------------------------------------------
__device__ float g_v[(size_t)M_ * D_];   // fp32 V (needs transpose-split)

// Fragment-major pre-split bf16 operands (packed bf16x2 in u32)
#define A_FRAG_U32 ((size_t)(M_/16) * KC_N * 128)   // 4,194,304
#define B_FRAG_U32 ((size_t)(D_/8) * KC_N * 64)     // 2,097,152
__device__ unsigned g_xah[A_FRAG_U32], g_xal[A_FRAG_U32];
__device__ unsigned g_oah[A_FRAG_U32], g_oal[A_FRAG_U32];
__device__ unsigned g_wbh[4][B_FRAG_U32], g_wbl[4][B_FRAG_U32];

// Attention fragments, per (b,h):
// Q A-frag:   [bh 32][mt 128][kc 8][128]
// K B-frag:   [bh 32][nt 256][kc 8][64]
// V B-frag(T):[bh 32][ntd 16][kcs 128][64]
#define QF_U32 ((size_t)32 * 128 * 8 * 128)
#define KF_U32 ((size_t)32 * 256 * 8 * 64)
#define VF_U32 ((size_t)32 * 16 * 128 * 64)
__device__ unsigned g_qfh[QF_U32], g_qfl[QF_U32];
__device__ unsigned g_kfh[KF_U32], g_kfl[KF_U32];
__device__ unsigned g_vfh[VF_U32], g_vfl[VF_U32];

// ---------------------------------------------------------------------------
// bf16 helpers (3xBF16 = near-fp32 precision; drops only lo*lo ~ 2^-18)
// ---------------------------------------------------------------------------
__device__ __forceinline__ unsigned pack2(float x, float y) {
    __nv_bfloat162 t = __floats2bfloat162_rn(x, y);   // x -> low half
    return *reinterpret_cast<unsigned*>(&t);
}
__device__ __forceinline__ void split2(float x, float y, unsigned &hi, unsigned &lo) {
    float hx = __bfloat162float(__float2bfloat16_rn(x));
    float hy = __bfloat162float(__float2bfloat16_rn(y));
    hi = pack2(hx, hy);
    lo = pack2(x - hx, y - hy);
}

__device__ __forceinline__ void mma_bf16(float* c, const unsigned* a, const unsigned* b) {
    asm volatile(
        "mma.sync.aligned.m16n8k16.row.col.f32.bf16.bf16.f32 "
        "{%0,%1,%2,%3}, {%4,%5,%6,%7}, {%8,%9}, {%0,%1,%2,%3};"
        : "+f"(c[0]), "+f"(c[1]), "+f"(c[2]), "+f"(c[3])
        : "r"(a[0]), "r"(a[1]), "r"(a[2]), "r"(a[3]),
          "r"(b[0]), "r"(b[1]));
}

__device__ __forceinline__ void cp16(unsigned s, const void* g) {
    asm volatile("cp.async.cg.shared.global [%0], [%1], 16;\n" :: "r"(s), "l"(g));
}
__device__ __forceinline__ void cp_commit() {
    asm volatile("cp.async.commit_group;\n" ::: "memory");
}
__device__ __forceinline__ void cp_wait1() {
    asm volatile("cp.async.wait_group 1;\n" ::: "memory");
}

// ---------------------------------------------------------------------------
// Split kernels (row-major fp32 -> fragment-major packed bf16 hi/lo)
// ---------------------------------------------------------------------------
// A split (x only now). grid (R/64, 64), 256 threads.
__global__ __launch_bounds__(256) void split_a_kernel(
    const float* __restrict__ src, unsigned* __restrict__ dhi, unsigned* __restrict__ dlo)
{
    __shared__ float S[64][33];
    const int tid = threadIdx.x;
    const int row0 = blockIdx.x * 64;
    const int col0 = blockIdx.y * 32;
    #pragma unroll
    for (int i = 0; i < 8; i++) {
        int lin = tid + i * 256;
        int r = lin >> 5, c = lin & 31;
        S[r][c] = src[(size_t)(row0 + r) * D_ + col0 + c];
    }
    __syncthreads();
    const int warp = tid >> 5, lane = tid & 31;
    const int g = lane >> 2, tg = lane & 3;
    const int mt = warp >> 1, kc = warp & 1;
    const int m0 = mt * 16, k0 = kc * 16;
    uint4 hi, lo;
    split2(S[m0 + g    ][k0 + 2*tg    ], S[m0 + g    ][k0 + 2*tg + 1], hi.x, lo.x);
    split2(S[m0 + 8 + g][k0 + 2*tg    ], S[m0 + 8 + g][k0 + 2*tg + 1], hi.y, lo.y);
    split2(S[m0 + g    ][k0 + 2*tg + 8], S[m0 + g    ][k0 + 2*tg + 9], hi.z, lo.z);
    split2(S[m0 + 8 + g][k0 + 2*tg + 8], S[m0 + 8 + g][k0 + 2*tg + 9], hi.w, lo.w);
    size_t base = ((size_t)(blockIdx.x*4 + mt) * KC_N + (blockIdx.y*2 + kc)) * 128 + lane * 4;
    *(uint4*)(dhi + base) = hi;
    *(uint4*)(dlo + base) = lo;
}

// B split (weights, batched over 4 slabs via blockIdx.z). grid (32, 64, 4).
__global__ __launch_bounds__(256) void split_b_kernel(
    const float* __restrict__ w0, const float* __restrict__ w1,
    const float* __restrict__ w2, const float* __restrict__ w3,
    unsigned* __restrict__ dhi_base, unsigned* __restrict__ dlo_base)
{
    __shared__ float S[64][33];
    const int tid = threadIdx.x;
    const int z = blockIdx.z;
    const float* src = (z == 0) ? w0 : (z == 1) ? w1 : (z == 2) ? w2 : w3;
    unsigned* dhi = dhi_base + (size_t)z * B_FRAG_U32;
    unsigned* dlo = dlo_base + (size_t)z * B_FRAG_U32;
    const int row0 = blockIdx.x * 64;
    const int col0 = blockIdx.y * 32;
    #pragma unroll
    for (int i = 0; i < 8; i++) {
        int lin = tid + i * 256;
        int r = lin >> 5, c = lin & 31;
        S[r][c] = src[(size_t)(row0 + r) * D_ + col0 + c];
    }
    __syncthreads();
    const int warp = tid >> 5, lane = tid & 31;
    const int g = lane >> 2, tg = lane & 3;
    #pragma unroll
    for (int it = 0; it < 2; it++) {
        int t = warp * 2 + it;
        int nt = t >> 1, kc = t & 1;
        int n0 = nt * 8, k0 = kc * 16;
        uint2 hi, lo;
        split2(S[n0 + g][k0 + 2*tg    ], S[n0 + g][k0 + 2*tg + 1], hi.x, lo.x);
        split2(S[n0 + g][k0 + 2*tg + 8], S[n0 + g][k0 + 2*tg + 9], hi.y, lo.y);
        size_t base = ((size_t)(blockIdx.x*8 + nt) * KC_N + (blockIdx.y*2 + kc)) * 64 + lane * 2;
        *(uint2*)(dhi + base) = hi;
        *(uint2*)(dlo + base) = lo;
    }
}

// V transposed split: B-frag with n = headdim, k = seqpos. grid (32, 4, 32).
__global__ __launch_bounds__(256) void split_v_frag(
    const float* __restrict__ src, unsigned* __restrict__ dhi, unsigned* __restrict__ dlo)
{
    __shared__ float S[64][33];
    const int tid = threadIdx.x;
    const int bh = blockIdx.z;
    const int b = bh >> 4, h = bh & 15;
    const int row0 = b * S_ + blockIdx.x * 64;   // seq
    const int col0 = h * HD_ + blockIdx.y * 32;  // headdim
    #pragma unroll
    for (int i = 0; i < 8; i++) {
        int lin = tid + i * 256;
        int r = lin >> 5, c = lin & 31;
        S[r][c] = src[(size_t)(row0 + r) * D_ + col0 + c];
    }
    __syncthreads();
    const int warp = tid >> 5, lane = tid & 31;
    const int g = lane >> 2, tg = lane & 3;
    #pragma unroll
    for (int it = 0; it < 2; it++) {
        int t = warp * 2 + it;
        int ntl = t & 3, ks = t >> 2;
        int s0 = ks * 16, d0 = ntl * 8;
        uint2 hi, lo;
        split2(S[s0 + 2*tg    ][d0 + g], S[s0 + 2*tg + 1][d0 + g], hi.x, lo.x);
        split2(S[s0 + 2*tg + 8][d0 + g], S[s0 + 2*tg + 9][d0 + g], hi.y, lo.y);
        size_t base = (((size_t)bh*16 + blockIdx.y*4 + ntl) * 128 + (blockIdx.x*4 + ks)) * 64 + lane * 2;
        *(uint2*)(dhi + base) = hi;
        *(uint2*)(dlo + base) = lo;
    }
}

// ---------------------------------------------------------------------------
// GEMM (TN) on pre-split bf16 fragments, 3xBF16.  C[m,n] = sum_d A[m,d]*W[n,d]
// Block 128x128, BK=32 (2 k-chunks), 256 threads = 8 warps (2m x 4n).
// Fused over blockIdx.z: weight slab + output mode.
// fragMask bit z set -> epilogue writes attention fragments directly:
//   z=0: RoPE + Q A-frag;  z=1: RoPE + K B-frag.  Otherwise fp32 row-major.
// ---------------------------------------------------------------------------
#define GEMM_SMEM_BYTES (2 * 8192 * 4)   // 65536

__global__ __launch_bounds__(256) void gemm_frag_rope(
    const unsigned* __restrict__ Ahi, const unsigned* __restrict__ Alo,
    const unsigned* __restrict__ Bh_base, const unsigned* __restrict__ Bl_base,
    float* __restrict__ outF,
    unsigned* __restrict__ qfh_, unsigned* __restrict__ qfl_,
    unsigned* __restrict__ kfh_, unsigned* __restrict__ kfl_,
    const float* __restrict__ fc, int fragMask)
{
    extern __shared__ unsigned smu[];
    const int z = blockIdx.z;
    const unsigned* Bhi = Bh_base + (size_t)z * B_FRAG_U32;
    const unsigned* Blo = Bl_base + (size_t)z * B_FRAG_U32;

    const int tid  = threadIdx.x;
    const int warp = tid >> 5, lane = tid & 31;
    const int wm = warp >> 2, wn = warp & 3;
    const int g  = lane >> 2, tg = lane & 3;
    const int MT0 = blockIdx.x * 8;    // 8 mtiles per block
    const int NT0 = blockIdx.y * 16;   // 16 ntiles per block

    float acc[4][4][4];
    #pragma unroll
    for (int i = 0; i < 4; i++)
        #pragma unroll
        for (int j = 0; j < 4; j++)
            #pragma unroll
            for (int f = 0; f < 4; f++) acc[i][j][f] = 0.f;

    unsigned sbase = (unsigned)__cvta_generic_to_shared(smu);

    auto copy_tile = [&](int kt, int b) {
        unsigned soff = sbase + b * 8192u * 4u;
        #pragma unroll
        for (int i = 0; i < 2; i++) {
            int id = tid + i * 256;
            int tile = id >> 5, pos = id & 31;
            size_t gb = ((size_t)(MT0 + (tile >> 1)) * KC_N + kt*2 + (tile & 1)) * 128 + pos * 4;
            unsigned so = soff + (unsigned)(tile * 128 + pos * 4) * 4u;
            cp16(so,               Ahi + gb);
            cp16(so + 2048u * 4u,  Alo + gb);
        }
        #pragma unroll
        for (int i = 0; i < 2; i++) {
            int id = tid + i * 256;
            int tile = id >> 4, pos = id & 15;
            size_t gb = ((size_t)(NT0 + (tile >> 1)) * KC_N + kt*2 + (tile & 1)) * 64 + pos * 4;
            unsigned so = soff + (unsigned)(4096 + tile * 64 + pos * 4) * 4u;
            cp16(so,               Bhi + gb);
            cp16(so + 2048u * 4u,  Blo + gb);
        }
    };

    copy_tile(0, 0);
    cp_commit();

    for (int kt = 0; kt < NK_; kt++) {
        if (kt + 1 < NK_) copy_tile(kt + 1, (kt + 1) & 1);
        cp_commit();
        cp_wait1();
        __syncthreads();

        const unsigned* buf = smu + (kt & 1) * 8192;
        const uint4* As_h = (const uint4*)(buf);
        const uint4* As_l = (const uint4*)(buf + 2048);
        const uint2* Bs_h = (const uint2*)(buf + 4096);
        const uint2* Bs_l = (const uint2*)(buf + 6144);

        #pragma unroll
        for (int kc = 0; kc < 2; kc++) {
            uint4 ah[4], al[4];
            #pragma unroll
            for (int mt = 0; mt < 4; mt++) {
                int idx = ((wm*4 + mt)*2 + kc) * 32 + lane;
                ah[mt] = As_h[idx];
                al[mt] = As_l[idx];
            }
            uint2 bh[4], bl[4];
            #pragma unroll
            for (int nt = 0; nt < 4; nt++) {
                int idx = ((wn*4 + nt)*2 + kc) * 32 + lane;
                bh[nt] = Bs_h[idx];
                bl[nt] = Bs_l[idx];
            }
            #pragma unroll
            for (int mt = 0; mt < 4; mt++)
                #pragma unroll
                for (int nt = 0; nt < 4; nt++) {
                    mma_bf16(acc[mt][nt], (const unsigned*)&ah[mt], (const unsigned*)&bl[nt]);
                    mma_bf16(acc[mt][nt], (const unsigned*)&al[mt], (const unsigned*)&bh[nt]);
                    mma_bf16(acc[mt][nt], (const unsigned*)&ah[mt], (const unsigned*)&bh[nt]);
                }
        }
        __syncthreads();
    }

    const int bm = blockIdx.x * 128, bn = blockIdx.y * 128;

    if ((fragMask >> z) & 1) {
        // Fused epilogue: RoPE + bf16 split + direct fragment store (Q or K).
        #pragma unroll
        for (int mt = 0; mt < 4; mt++) {
            const int mrow_tile = blockIdx.x*8 + wm*4 + mt;   // global 16-row tile
            const int bb = mrow_tile >> 7;
            const int seq_mt = mrow_tile & 127;
            const int s_a = seq_mt*16 + g;
            const int s_b = s_a + 8;
            #pragma unroll
            for (int j = 0; j < 2; j++) {
                const int n0 = bn + wn*32 + j*16;
                const int h  = n0 >> 7;
                const int kc = (n0 & 127) >> 4;
                const int bh = bb*16 + h;
                const int j0 = kc*8 + tg, j1 = j0 + 4;
                float ca0 = fc[s_a*HD_ + j0*2], sa0 = fc[s_a*HD_ + j0*2 + 1];
                float cb0 = fc[s_b*HD_ + j0*2], sb0 = fc[s_b*HD_ + j0*2 + 1];
                float ca1 = fc[s_a*HD_ + j1*2], sa1 = fc[s_a*HD_ + j1*2 + 1];
                float cb1 = fc[s_b*HD_ + j1*2], sb1 = fc[s_b*HD_ + j1*2 + 1];
                float x0 = acc[mt][2*j][0]*ca0 - acc[mt][2*j][1]*sa0;
                float x1 = acc[mt][2*j][0]*sa0 + acc[mt][2*j][1]*ca0;
                float y0 = acc[mt][2*j][2]*cb0 - acc[mt][2*j][3]*sb0;
                float y1 = acc[mt][2*j][2]*sb0 + acc[mt][2*j][3]*cb0;
                float z0 = acc[mt][2*j+1][0]*ca1 - acc[mt][2*j+1][1]*sa1;
                float z1 = acc[mt][2*j+1][0]*sa1 + acc[mt][2*j+1][1]*ca1;
                float w0 = acc[mt][2*j+1][2]*cb1 - acc[mt][2*j+1][3]*sb1;
                float w1 = acc[mt][2*j+1][2]*sb1 + acc[mt][2*j+1][3]*cb1;
                if (z == 0) {
                    uint4 hi, lo;
                    split2(x0, x1, hi.x, lo.x);
                    split2(y0, y1, hi.y, lo.y);
                    split2(z0, z1, hi.z, lo.z);
                    split2(w0, w1, hi.w, lo.w);
                    size_t base = (((size_t)bh*128 + seq_mt)*8 + kc)*128 + lane*4;
                    *(uint4*)(qfh_ + base) = hi;
                    *(uint4*)(qfl_ + base) = lo;
                } else {
                    uint2 hiA, loA, hiB, loB;
                    split2(x0, x1, hiA.x, loA.x);   // seq row g,    head 2tg pair
                    split2(z0, z1, hiA.y, loA.y);   // seq row g,    head 2tg+8 pair
                    split2(y0, y1, hiB.x, loB.x);   // seq row g+8
                    split2(w0, w1, hiB.y, loB.y);
                    size_t baseA = (((size_t)bh*256 + seq_mt*2    )*8 + kc)*64 + lane*2;
                    size_t baseB = (((size_t)bh*256 + seq_mt*2 + 1)*8 + kc)*64 + lane*2;
                    *(uint2*)(kfh_ + baseA) = hiA;
                    *(uint2*)(kfl_ + baseA) = loA;
                    *(uint2*)(kfh_ + baseB) = hiB;
                    *(uint2*)(kfl_ + baseB) = loB;
                }
            }
        }
    } else {
        // fp32 row-major epilogue (V and output projection; no RoPE).
        #pragma unroll
        for (int mt = 0; mt < 4; mt++) {
            #pragma unroll
            for (int half = 0; half < 2; half++) {
                const int m = bm + wm * 64 + mt * 16 + g + half * 8;
                #pragma unroll
                for (int nt = 0; nt < 4; nt++) {
                    const int n = bn + wn * 32 + nt * 8 + 2 * tg;
                    *(float2*)(outF + (size_t)m * D_ + n) =
                        make_float2(acc[mt][nt][half*2 + 0], acc[mt][nt][half*2 + 1]);
                }
            }
        }
    }
}

// ---------------------------------------------------------------------------
// Tensor-core flash attention (causal, 3xBF16).
// Grid (S/64, NH, B), 128 threads = 4 warps; warp w owns q rows [w*16, w*16+16).
// kv-tile 32, double-buffered cp.async. qi reversed (heavy tiles first).
// Output written DIRECTLY as A-fragments for the output projection.
// ---------------------------------------------------------------------------
#define ATT2_SMEM_BYTES (26752 * 4)

__global__ __launch_bounds__(128) void attention_mma(
    const unsigned* __restrict__ Qh_, const unsigned* __restrict__ Ql_,
    const unsigned* __restrict__ Kh_, const unsigned* __restrict__ Kl_,
    const unsigned* __restrict__ Vh_, const unsigned* __restrict__ Vl_,
    unsigned* __restrict__ Oh_, unsigned* __restrict__ Ol_)
{
    extern __shared__ unsigned smu[];
    unsigned* Qh = smu;              // [mt 4][kc 8][128]
    unsigned* Ql = smu + 4096;
    unsigned* KV = smu + 8192;       // 2 x { Kh 2048 | Kl 2048 | Vh 2048 | Vl 2048 }
    unsigned* PsHi = smu + 24576;    // [64][17]
    unsigned* PsLo = smu + 25664;

    const int tid  = threadIdx.x;
    const int warp = tid >> 5, lane = tid & 31;
    const int g = lane >> 2, tg = lane & 3;
    const int qi = (int)gridDim.x - 1 - (int)blockIdx.x;   // heavy tiles first
    const int bh = blockIdx.z * NH_ + blockIdx.y;
    const int Q0 = qi * 64;
    const float scale = 0.08838834764831845f;   // 1/sqrt(128)

    {
        size_t qbase = ((size_t)bh * 128 + qi * 4) * 1024;
        const uint4* srch = (const uint4*)(Qh_ + qbase);
        const uint4* srcl = (const uint4*)(Ql_ + qbase);
        for (int i = tid; i < 1024; i += 128) {
            ((uint4*)Qh)[i] = srch[i];
            ((uint4*)Ql)[i] = srcl[i];
        }
    }

    unsigned kvbase = (unsigned)__cvta_generic_to_shared(KV);

    auto copy_kv = [&](int kt, int b) {
        unsigned soff = kvbase + (unsigned)b * 8192u * 4u;
        size_t kbase = ((size_t)bh * 256 + kt * 4) * 512;
        for (int i = tid; i < 512; i += 128) {
            cp16(soff + i * 16u,               Kh_ + kbase + i * 4);
            cp16(soff + 2048u*4u + i * 16u,    Kl_ + kbase + i * 4);
        }
        for (int i = tid; i < 512; i += 128) {
            int tile = i >> 4, pos = i & 15;
            size_t vb = (((size_t)bh * 16 + (tile >> 1)) * 128 + (size_t)kt * 2 + (tile & 1)) * 64 + pos * 4;
            cp16(soff + 4096u*4u + i * 16u,    Vh_ + vb);
            cp16(soff + 6144u*4u + i * 16u,    Vl_ + vb);
        }
    };

    float m0 = -1e30f, m1 = -1e30f, l0 = 0.f, l1 = 0.f;
    float o[16][4];
    #pragma unroll
    for (int nt = 0; nt < 16; nt++)
        #pragma unroll
        for (int f = 0; f < 4; f++) o[nt][f] = 0.f;

    const int ktmax = 2 * qi + 2;
    copy_kv(0, 0);
    cp_commit();
    __syncthreads();

    const int prow0 = warp * 16 + g;
    const int prow1 = prow0 + 8;
    const int qrow0 = Q0 + prow0;

    for (int kt = 0; kt < ktmax; kt++) {
        if (kt + 1 < ktmax) copy_kv(kt + 1, (kt + 1) & 1);
        cp_commit();
        cp_wait1();
        __syncthreads();

        const unsigned* Kh_s = KV + (kt & 1) * 8192;
        const unsigned* Kl_s = Kh_s + 2048;
        const unsigned* Vh_s = Kh_s + 4096;
        const unsigned* Vl_s = Kh_s + 6144;

        float s[4][4];
        #pragma unroll
        for (int nt = 0; nt < 4; nt++)
            #pragma unroll
            for (int f = 0; f < 4; f++) s[nt][f] = 0.f;

        #pragma unroll
        for (int kc = 0; kc < 8; kc++) {
            uint4 ah = *(const uint4*)(Qh + (warp*8 + kc) * 128 + lane * 4);
            uint4 al = *(const uint4*)(Ql + (warp*8 + kc) * 128 + lane * 4);
            #pragma unroll
            for (int nt = 0; nt < 4; nt++) {
                uint2 kbh = *(const uint2*)(Kh_s + (nt*8 + kc) * 64 + lane * 2);
                uint2 kbl = *(const uint2*)(Kl_s + (nt*8 + kc) * 64 + lane * 2);
                mma_bf16(s[nt], (const unsigned*)&ah, (const unsigned*)&kbl);
                mma_bf16(s[nt], (const unsigned*)&al, (const unsigned*)&kbh);
                mma_bf16(s[nt], (const unsigned*)&ah, (const unsigned*)&kbh);
            }
        }

        const bool needMask = (kt >= 2 * qi);
        float mloc0 = -1e30f, mloc1 = -1e30f;
        #pragma unroll
        for (int nt = 0; nt < 4; nt++) {
            #pragma unroll
            for (int j = 0; j < 2; j++) {
                int col = kt*32 + nt*8 + 2*tg + j;
                float sv0 = s[nt][j]   * scale;
                float sv1 = s[nt][2+j] * scale;
                if (needMask) {
                    if (col > qrow0)     sv0 = -1e30f;
                    if (col > qrow0 + 8) sv1 = -1e30f;
                }
                s[nt][j] = sv0; s[nt][2+j] = sv1;
                mloc0 = fmaxf(mloc0, sv0);
                mloc1 = fmaxf(mloc1, sv1);
            }
        }
        mloc0 = fmaxf(mloc0, __shfl_xor_sync(0xffffffffu, mloc0, 1));
        mloc0 = fmaxf(mloc0, __shfl_xor_sync(0xffffffffu, mloc0, 2));
        mloc1 = fmaxf(mloc1, __shfl_xor_sync(0xffffffffu, mloc1, 1));
        mloc1 = fmaxf(mloc1, __shfl_xor_sync(0xffffffffu, mloc1, 2));

        float mn0 = fmaxf(m0, mloc0), mn1 = fmaxf(m1, mloc1);
        float corr0 = __expf(m0 - mn0), corr1 = __expf(m1 - mn1);
        float ls0 = 0.f, ls1 = 0.f;
        #pragma unroll
        for (int nt = 0; nt < 4; nt++) {
            #pragma unroll
            for (int j = 0; j < 2; j++) {
                float p0 = __expf(s[nt][j]   - mn0);
                float p1 = __expf(s[nt][2+j] - mn1);
                s[nt][j] = p0; s[nt][2+j] = p1;
                ls0 += p0; ls1 += p1;
            }
        }
        ls0 += __shfl_xor_sync(0xffffffffu, ls0, 1);
        ls0 += __shfl_xor_sync(0xffffffffu, ls0, 2);
        ls1 += __shfl_xor_sync(0xffffffffu, ls1, 1);
        ls1 += __shfl_xor_sync(0xffffffffu, ls1, 2);
        l0 = l0 * corr0 + ls0;  m0 = mn0;
        l1 = l1 * corr1 + ls1;  m1 = mn1;

        #pragma unroll
        for (int nt = 0; nt < 16; nt++) {
            o[nt][0] *= corr0; o[nt][1] *= corr0;
            o[nt][2] *= corr1; o[nt][3] *= corr1;
        }

        #pragma unroll
        for (int nt = 0; nt < 4; nt++) {
            unsigned hi, lo;
            split2(s[nt][0], s[nt][1], hi, lo);
            PsHi[prow0*17 + nt*4 + tg] = hi;
            PsLo[prow0*17 + nt*4 + tg] = lo;
            split2(s[nt][2], s[nt][3], hi, lo);
            PsHi[prow1*17 + nt*4 + tg] = hi;
            PsLo[prow1*17 + nt*4 + tg] = lo;
        }
        __syncwarp();

        #pragma unroll
        for (int kc = 0; kc < 2; kc++) {
            unsigned phi[4] = { PsHi[prow0*17 + kc*8 + tg],     PsHi[prow1*17 + kc*8 + tg],
                                PsHi[prow0*17 + kc*8 + 4 + tg], PsHi[prow1*17 + kc*8 + 4 + tg] };
            unsigned plo[4] = { PsLo[prow0*17 + kc*8 + tg],     PsLo[prow1*17 + kc*8 + tg],
                                PsLo[prow0*17 + kc*8 + 4 + tg], PsLo[prow1*17 + kc*8 + 4 + tg] };
            #pragma unroll
            for (int nt = 0; nt < 16; nt++) {
                uint2 vh = *(const uint2*)(Vh_s + (nt*2 + kc) * 64 + lane * 2);
                uint2 vl = *(const uint2*)(Vl_s + (nt*2 + kc) * 64 + lane * 2);
                mma_bf16(o[nt], phi, (const unsigned*)&vl);
                mma_bf16(o[nt], plo, (const unsigned*)&vh);
                mma_bf16(o[nt], phi, (const unsigned*)&vh);
            }
        }
        __syncthreads();
    }

    // ---- normalize + split + store directly as output-projection A-frags ----
    float inv0 = 1.0f / l0, inv1 = 1.0f / l1;
    const int b = bh >> 4, h = bh & 15;
    const int mtile = b * 128 + qi * 4 + warp;   // global 16-row tile index
    #pragma unroll
    for (int j = 0; j < 8; j++) {
        uint4 hi, lo;
        split2(o[2*j  ][0]*inv0, o[2*j  ][1]*inv0, hi.x, lo.x);
        split2(o[2*j  ][2]*inv1, o[2*j  ][3]*inv1, hi.y, lo.y);
        split2(o[2*j+1][0]*inv0, o[2*j+1][1]*inv0, hi.z, lo.z);
        split2(o[2*j+1][2]*inv1, o[2*j+1][3]*inv1, hi.w, lo.w);
        size_t base = ((size_t)mtile * KC_N + (h*8 + j)) * 128 + lane * 4;
        *(uint4*)(Oh_ + base) = hi;
        *(uint4*)(Ol_ + base) = lo;
    }
}

// ---------------------------------------------------------------------------
// Launch. Inputs: x, start_pos, freqs_cis, mask, wq, wk, wv, wo
// ---------------------------------------------------------------------------
extern "C" void kernel_launch(void* const* d_in, const int* in_sizes, int n_in,
                              void* d_out, int out_size) {
    (void)in_sizes; (void)n_in; (void)out_size;
    const float* x  = (const float*)d_in[0];
    const float* fc = (const float*)d_in[2];
    const float* w[4] = { (const float*)d_in[4], (const float*)d_in[5],
                          (const float*)d_in[6], (const float*)d_in[7] };
    float* out = (float*)d_out;

    float *v;
    unsigned *xah, *xal, *oah, *oal, *wbh, *wbl;
    unsigned *qfh, *qfl, *kfh, *kfl, *vfh, *vfl;
    cudaGetSymbolAddress((void**)&v,    g_v);
    cudaGetSymbolAddress((void**)&xah,  g_xah);
    cudaGetSymbolAddress((void**)&xal,  g_xal);
    cudaGetSymbolAddress((void**)&oah,  g_oah);
    cudaGetSymbolAddress((void**)&oal,  g_oal);
    cudaGetSymbolAddress((void**)&wbh,  g_wbh);
    cudaGetSymbolAddress((void**)&wbl,  g_wbl);
    cudaGetSymbolAddress((void**)&qfh,  g_qfh);
    cudaGetSymbolAddress((void**)&qfl,  g_qfl);
    cudaGetSymbolAddress((void**)&kfh,  g_kfh);
    cudaGetSymbolAddress((void**)&kfl,  g_kfl);
    cudaGetSymbolAddress((void**)&vfh,  g_vfh);
    cudaGetSymbolAddress((void**)&vfl,  g_vfl);

    cudaFuncSetAttribute(gemm_frag_rope,
                         cudaFuncAttributeMaxDynamicSharedMemorySize, GEMM_SMEM_BYTES);
    cudaFuncSetAttribute(attention_mma,
                         cudaFuncAttributeMaxDynamicSharedMemorySize, ATT2_SMEM_BYTES);

    // Pre-split operands
    split_a_kernel<<<dim3(M_/64, D_/32), 256>>>(x, xah, xal);
    split_b_kernel<<<dim3(D_/64, D_/32, 4), 256>>>(w[0], w[1], w[2], w[3], wbh, wbl);

    // Fused Q/K/V projections: z=0 -> Q frags (RoPE), z=1 -> K frags (RoPE),
    // z=2 -> fp32 V.
    dim3 gemm_grid(M_/128, D_/128, 3);   // (32, 16, 3)
    gemm_frag_rope<<<gemm_grid, 256, GEMM_SMEM_BYTES>>>(xah, xal, wbh, wbl,
        v, qfh, qfl, kfh, kfl, fc, 0b011);

    // V transpose-split (only remaining layout shuffle)
    dim3 sgrid(S_/64, HD_/32, B_*NH_);   // (32, 4, 32)
    split_v_frag<<<sgrid, 256>>>(v, vfh, vfl);

    // Tensor-core flash attention; writes output-projection A-frags directly
    dim3 att_grid(S_/64, NH_, B_);       // (32, 16, 2)
    attention_mma<<<att_grid, 128, ATT2_SMEM_BYTES>>>(qfh, qfl, kfh, kfl, vfh, vfl,
                                                      oah, oal);

    // Output projection (fp32 epilogue, no rope, weight slab 3 via z=0 + offset)
    dim3 o_grid(M_/128, D_/128, 1);
    gemm_frag_rope<<<o_grid, 256, GEMM_SMEM_BYTES>>>(oah, oal,
        wbh + 3*B_FRAG_U32, wbl + 3*B_FRAG_U32, out, qfh, qfl, kfh, kfl, fc, 0);
}

// round 12
// speedup vs baseline: 1.0700x; 1.0700x over previous
#include <cuda_runtime.h>
#include <cuda_bf16.h>
#include <math.h>

// Problem constants
#define B_   2
#define S_   2048
#define D_   2048
#define NH_  16
#define HD_  128
#define M_   (B_*S_)          // 4096 total rows
#define KC_N (D_/16)          // 128 k16-chunks per row
#define NK_  (D_/32)          // 64 k-iterations of BK=32

// ---------------------------------------------------------------------------
// Scratch (static device globals — no runtime allocation allowed)
// ---------------------------------------------------------------------------
__device__ float g_q[(size_t)M_ * D_];
__device__ float g_k[(size_t)M_ * D_];
__device__ float g_v[(size_t)M_ * D_];

// Fragment-major pre-split bf16 operands (packed bf16x2 in u32)
#define A_FRAG_U32 ((size_t)(M_/16) * KC_N * 128)   // 4,194,304
#define B_FRAG_U32 ((size_t)(D_/8) * KC_N * 64)     // 2,097,152
__device__ unsigned g_xah[A_FRAG_U32], g_xal[A_FRAG_U32];
__device__ unsigned g_oah[A_FRAG_U32], g_oal[A_FRAG_U32];
__device__ unsigned g_wbh[4][B_FRAG_U32], g_wbl[4][B_FRAG_U32];

// Attention fragments, per (b,h):
// Q A-frag:   [bh 32][mt 128][kc 8][128]
// K B-frag:   [bh 32][nt 256][kc 8][64]
// V B-frag(T):[bh 32][ntd 16][kcs 128][64]
#define QF_U32 ((size_t)32 * 128 * 8 * 128)
#define KF_U32 ((size_t)32 * 256 * 8 * 64)
#define VF_U32 ((size_t)32 * 16 * 128 * 64)
__device__ unsigned g_qfh[QF_U32], g_qfl[QF_U32];
__device__ unsigned g_kfh[KF_U32], g_kfl[KF_U32];
__device__ unsigned g_vfh[VF_U32], g_vfl[VF_U32];

// ---------------------------------------------------------------------------
// bf16 helpers (3xBF16 = near-fp32 precision; drops only lo*lo ~ 2^-18)
// ---------------------------------------------------------------------------
__device__ __forceinline__ unsigned pack2(float x, float y) {
    __nv_bfloat162 t = __floats2bfloat162_rn(x, y);   // x -> low half
    return *reinterpret_cast<unsigned*>(&t);
}
__device__ __forceinline__ void split2(float x, float y, unsigned &hi, unsigned &lo) {
    float hx = __bfloat162float(__float2bfloat16_rn(x));
    float hy = __bfloat162float(__float2bfloat16_rn(y));
    hi = pack2(hx, hy);
    lo = pack2(x - hx, y - hy);
}

__device__ __forceinline__ void mma_bf16(float* c, const unsigned* a, const unsigned* b) {
    asm volatile(
        "mma.sync.aligned.m16n8k16.row.col.f32.bf16.bf16.f32 "
        "{%0,%1,%2,%3}, {%4,%5,%6,%7}, {%8,%9}, {%0,%1,%2,%3};"
        : "+f"(c[0]), "+f"(c[1]), "+f"(c[2]), "+f"(c[3])
        : "r"(a[0]), "r"(a[1]), "r"(a[2]), "r"(a[3]),
          "r"(b[0]), "r"(b[1]));
}

__device__ __forceinline__ void cp16(unsigned s, const void* g) {
    asm volatile("cp.async.cg.shared.global [%0], [%1], 16;\n" :: "r"(s), "l"(g));
}
__device__ __forceinline__ void cp_commit() {
    asm volatile("cp.async.commit_group;\n" ::: "memory");
}
__device__ __forceinline__ void cp_wait1() {
    asm volatile("cp.async.wait_group 1;\n" ::: "memory");
}

// ---------------------------------------------------------------------------
// Split kernels (row-major fp32 -> fragment-major packed bf16 hi/lo)
// ---------------------------------------------------------------------------
// A split (x). grid (R/64, 64), 256 threads.
__global__ __launch_bounds__(256) void split_a_kernel(
    const float* __restrict__ src, unsigned* __restrict__ dhi, unsigned* __restrict__ dlo)
{
    __shared__ float S[64][33];
    const int tid = threadIdx.x;
    const int row0 = blockIdx.x * 64;
    const int col0 = blockIdx.y * 32;
    #pragma unroll
    for (int i = 0; i < 8; i++) {
        int lin = tid + i * 256;
        int r = lin >> 5, c = lin & 31;
        S[r][c] = src[(size_t)(row0 + r) * D_ + col0 + c];
    }
    __syncthreads();
    const int warp = tid >> 5, lane = tid & 31;
    const int g = lane >> 2, tg = lane & 3;
    const int mt = warp >> 1, kc = warp & 1;
    const int m0 = mt * 16, k0 = kc * 16;
    uint4 hi, lo;
    split2(S[m0 + g    ][k0 + 2*tg    ], S[m0 + g    ][k0 + 2*tg + 1], hi.x, lo.x);
    split2(S[m0 + 8 + g][k0 + 2*tg    ], S[m0 + 8 + g][k0 + 2*tg + 1], hi.y, lo.y);
    split2(S[m0 + g    ][k0 + 2*tg + 8], S[m0 + g    ][k0 + 2*tg + 9], hi.z, lo.z);
    split2(S[m0 + 8 + g][k0 + 2*tg + 8], S[m0 + 8 + g][k0 + 2*tg + 9], hi.w, lo.w);
    size_t base = ((size_t)(blockIdx.x*4 + mt) * KC_N + (blockIdx.y*2 + kc)) * 128 + lane * 4;
    *(uint4*)(dhi + base) = hi;
    *(uint4*)(dlo + base) = lo;
}

// B split (weights, batched over 4 slabs via blockIdx.z). grid (32, 64, 4).
__global__ __launch_bounds__(256) void split_b_kernel(
    const float* __restrict__ w0, const float* __restrict__ w1,
    const float* __restrict__ w2, const float* __restrict__ w3,
    unsigned* __restrict__ dhi_base, unsigned* __restrict__ dlo_base)
{
    __shared__ float S[64][33];
    const int tid = threadIdx.x;
    const int z = blockIdx.z;
    const float* src = (z == 0) ? w0 : (z == 1) ? w1 : (z == 2) ? w2 : w3;
    unsigned* dhi = dhi_base + (size_t)z * B_FRAG_U32;
    unsigned* dlo = dlo_base + (size_t)z * B_FRAG_U32;
    const int row0 = blockIdx.x * 64;
    const int col0 = blockIdx.y * 32;
    #pragma unroll
    for (int i = 0; i < 8; i++) {
        int lin = tid + i * 256;
        int r = lin >> 5, c = lin & 31;
        S[r][c] = src[(size_t)(row0 + r) * D_ + col0 + c];
    }
    __syncthreads();
    const int warp = tid >> 5, lane = tid & 31;
    const int g = lane >> 2, tg = lane & 3;
    #pragma unroll
    for (int it = 0; it < 2; it++) {
        int t = warp * 2 + it;
        int nt = t >> 1, kc = t & 1;
        int n0 = nt * 8, k0 = kc * 16;
        uint2 hi, lo;
        split2(S[n0 + g][k0 + 2*tg    ], S[n0 + g][k0 + 2*tg + 1], hi.x, lo.x);
        split2(S[n0 + g][k0 + 2*tg + 8], S[n0 + g][k0 + 2*tg + 9], hi.y, lo.y);
        size_t base = ((size_t)(blockIdx.x*8 + nt) * KC_N + (blockIdx.y*2 + kc)) * 64 + lane * 2;
        *(uint2*)(dhi + base) = hi;
        *(uint2*)(dlo + base) = lo;
    }
}

// Q split per (b,h). grid (32, 4, 32).
__global__ __launch_bounds__(256) void split_q_frag(
    const float* __restrict__ src, unsigned* __restrict__ dhi, unsigned* __restrict__ dlo)
{
    __shared__ float S[64][33];
    const int tid = threadIdx.x;
    const int bh = blockIdx.z;
    const int b = bh >> 4, h = bh & 15;
    const int row0 = b * S_ + blockIdx.x * 64;
    const int col0 = h * HD_ + blockIdx.y * 32;
    #pragma unroll
    for (int i = 0; i < 8; i++) {
        int lin = tid + i * 256;
        int r = lin >> 5, c = lin & 31;
        S[r][c] = src[(size_t)(row0 + r) * D_ + col0 + c];
    }
    __syncthreads();
    const int warp = tid >> 5, lane = tid & 31;
    const int g = lane >> 2, tg = lane & 3;
    const int mt = warp >> 1, kc = warp & 1;
    const int m0 = mt * 16, k0 = kc * 16;
    uint4 hi, lo;
    split2(S[m0 + g    ][k0 + 2*tg    ], S[m0 + g    ][k0 + 2*tg + 1], hi.x, lo.x);
    split2(S[m0 + 8 + g][k0 + 2*tg    ], S[m0 + 8 + g][k0 + 2*tg + 1], hi.y, lo.y);
    split2(S[m0 + g    ][k0 + 2*tg + 8], S[m0 + g    ][k0 + 2*tg + 9], hi.z, lo.z);
    split2(S[m0 + 8 + g][k0 + 2*tg + 8], S[m0 + 8 + g][k0 + 2*tg + 9], hi.w, lo.w);
    size_t base = (((size_t)bh*128 + blockIdx.x*4 + mt) * 8 + (blockIdx.y*2 + kc)) * 128 + lane * 4;
    *(uint4*)(dhi + base) = hi;
    *(uint4*)(dlo + base) = lo;
}

// K split per (b,h). grid (32, 4, 32).
__global__ __launch_bounds__(256) void split_k_frag(
    const float* __restrict__ src, unsigned* __restrict__ dhi, unsigned* __restrict__ dlo)
{
    __shared__ float S[64][33];
    const int tid = threadIdx.x;
    const int bh = blockIdx.z;
    const int b = bh >> 4, h = bh & 15;
    const int row0 = b * S_ + blockIdx.x * 64;
    const int col0 = h * HD_ + blockIdx.y * 32;
    #pragma unroll
    for (int i = 0; i < 8; i++) {
        int lin = tid + i * 256;
        int r = lin >> 5, c = lin & 31;
        S[r][c] = src[(size_t)(row0 + r) * D_ + col0 + c];
    }
    __syncthreads();
    const int warp = tid >> 5, lane = tid & 31;
    const int g = lane >> 2, tg = lane & 3;
    #pragma unroll
    for (int it = 0; it < 2; it++) {
        int t = warp * 2 + it;
        int nt = t >> 1, kc = t & 1;
        int n0 = nt * 8, k0 = kc * 16;
        uint2 hi, lo;
        split2(S[n0 + g][k0 + 2*tg    ], S[n0 + g][k0 + 2*tg + 1], hi.x, lo.x);
        split2(S[n0 + g][k0 + 2*tg + 8], S[n0 + g][k0 + 2*tg + 9], hi.y, lo.y);
        size_t base = (((size_t)bh*256 + blockIdx.x*8 + nt) * 8 + (blockIdx.y*2 + kc)) * 64 + lane * 2;
        *(uint2*)(dhi + base) = hi;
        *(uint2*)(dlo + base) = lo;
    }
}

// V transposed split: B-frag with n = headdim, k = seqpos. grid (32, 4, 32).
__global__ __launch_bounds__(256) void split_v_frag(
    const float* __restrict__ src, unsigned* __restrict__ dhi, unsigned* __restrict__ dlo)
{
    __shared__ float S[64][33];
    const int tid = threadIdx.x;
    const int bh = blockIdx.z;
    const int b = bh >> 4, h = bh & 15;
    const int row0 = b * S_ + blockIdx.x * 64;   // seq
    const int col0 = h * HD_ + blockIdx.y * 32;  // headdim
    #pragma unroll
    for (int i = 0; i < 8; i++) {
        int lin = tid + i * 256;
        int r = lin >> 5, c = lin & 31;
        S[r][c] = src[(size_t)(row0 + r) * D_ + col0 + c];
    }
    __syncthreads();
    const int warp = tid >> 5, lane = tid & 31;
    const int g = lane >> 2, tg = lane & 3;
    #pragma unroll
    for (int it = 0; it < 2; it++) {
        int t = warp * 2 + it;
        int ntl = t & 3, ks = t >> 2;
        int s0 = ks * 16, d0 = ntl * 8;
        uint2 hi, lo;
        split2(S[s0 + 2*tg    ][d0 + g], S[s0 + 2*tg + 1][d0 + g], hi.x, lo.x);
        split2(S[s0 + 2*tg + 8][d0 + g], S[s0 + 2*tg + 9][d0 + g], hi.y, lo.y);
        size_t base = (((size_t)bh*16 + blockIdx.y*4 + ntl) * 128 + (blockIdx.x*4 + ks)) * 64 + lane * 2;
        *(uint2*)(dhi + base) = hi;
        *(uint2*)(dlo + base) = lo;
    }
}

// ---------------------------------------------------------------------------
// GEMM (TN) on pre-split bf16 fragments, 3xBF16 (R10 version, verbatim).
// Block 128x128, BK=32 (2 k-chunks), 256 threads = 8 warps (2m x 4n).
// Fused over blockIdx.z: selects weight slab + output + rope flag.
// ---------------------------------------------------------------------------
#define GEMM_SMEM_BYTES (2 * 8192 * 4)   // 65536

__global__ __launch_bounds__(256) void gemm_frag_rope(
    const unsigned* __restrict__ Ahi, const unsigned* __restrict__ Alo,
    const unsigned* __restrict__ Bh_base, const unsigned* __restrict__ Bl_base,
    float* __restrict__ out0, float* __restrict__ out1, float* __restrict__ out2,
    const float* __restrict__ fc, int ropeMask)
{
    extern __shared__ unsigned smu[];
    const int z = blockIdx.z;
    const unsigned* Bhi = Bh_base + (size_t)z * B_FRAG_U32;
    const unsigned* Blo = Bl_base + (size_t)z * B_FRAG_U32;
    float* C = (z == 0) ? out0 : ((z == 1) ? out1 : out2);
    const int applyRope = (ropeMask >> z) & 1;

    const int tid  = threadIdx.x;
    const int warp = tid >> 5, lane = tid & 31;
    const int wm = warp >> 2, wn = warp & 3;
    const int g  = lane >> 2, tg = lane & 3;
    const int MT0 = blockIdx.x * 8;    // 8 mtiles per block
    const int NT0 = blockIdx.y * 16;   // 16 ntiles per block

    float acc[4][4][4];
    #pragma unroll
    for (int i = 0; i < 4; i++)
        #pragma unroll
        for (int j = 0; j < 4; j++)
            #pragma unroll
            for (int f = 0; f < 4; f++) acc[i][j][f] = 0.f;

    unsigned sbase = (unsigned)__cvta_generic_to_shared(smu);

    auto copy_tile = [&](int kt, int b) {
        unsigned soff = sbase + b * 8192u * 4u;
        #pragma unroll
        for (int i = 0; i < 2; i++) {
            int id = tid + i * 256;
            int tile = id >> 5, pos = id & 31;
            size_t gb = ((size_t)(MT0 + (tile >> 1)) * KC_N + kt*2 + (tile & 1)) * 128 + pos * 4;
            unsigned so = soff + (unsigned)(tile * 128 + pos * 4) * 4u;
            cp16(so,               Ahi + gb);
            cp16(so + 2048u * 4u,  Alo + gb);
        }
        #pragma unroll
        for (int i = 0; i < 2; i++) {
            int id = tid + i * 256;
            int tile = id >> 4, pos = id & 15;
            size_t gb = ((size_t)(NT0 + (tile >> 1)) * KC_N + kt*2 + (tile & 1)) * 64 + pos * 4;
            unsigned so = soff + (unsigned)(4096 + tile * 64 + pos * 4) * 4u;
            cp16(so,               Bhi + gb);
            cp16(so + 2048u * 4u,  Blo + gb);
        }
    };

    copy_tile(0, 0);
    cp_commit();

    for (int kt = 0; kt < NK_; kt++) {
        if (kt + 1 < NK_) copy_tile(kt + 1, (kt + 1) & 1);
        cp_commit();
        cp_wait1();
        __syncthreads();

        const unsigned* buf = smu + (kt & 1) * 8192;
        const uint4* As_h = (const uint4*)(buf);
        const uint4* As_l = (const uint4*)(buf + 2048);
        const uint2* Bs_h = (const uint2*)(buf + 4096);
        const uint2* Bs_l = (const uint2*)(buf + 6144);

        #pragma unroll
        for (int kc = 0; kc < 2; kc++) {
            uint4 ah[4], al[4];
            #pragma unroll
            for (int mt = 0; mt < 4; mt++) {
                int idx = ((wm*4 + mt)*2 + kc) * 32 + lane;
                ah[mt] = As_h[idx];
                al[mt] = As_l[idx];
            }
            uint2 bh[4], bl[4];
            #pragma unroll
            for (int nt = 0; nt < 4; nt++) {
                int idx = ((wn*4 + nt)*2 + kc) * 32 + lane;
                bh[nt] = Bs_h[idx];
                bl[nt] = Bs_l[idx];
            }
            #pragma unroll
            for (int mt = 0; mt < 4; mt++)
                #pragma unroll
                for (int nt = 0; nt < 4; nt++) {
                    mma_bf16(acc[mt][nt], (const unsigned*)&ah[mt], (const unsigned*)&bl[nt]);
                    mma_bf16(acc[mt][nt], (const unsigned*)&al[mt], (const unsigned*)&bh[nt]);
                    mma_bf16(acc[mt][nt], (const unsigned*)&ah[mt], (const unsigned*)&bh[nt]);
                }
        }
        __syncthreads();
    }

    // Epilogue: c0,c1=(row,2tg),(row,2tg+1); c2,c3=row+8. RoPE pair = (2tg,2tg+1).
    const int bm = blockIdx.x * 128, bn = blockIdx.y * 128;
    #pragma unroll
    for (int mt = 0; mt < 4; mt++) {
        #pragma unroll
        for (int half = 0; half < 2; half++) {
            const int m = bm + wm * 64 + mt * 16 + g + half * 8;
            const int s = m & (S_ - 1);
            #pragma unroll
            for (int nt = 0; nt < 4; nt++) {
                const int n = bn + wn * 32 + nt * 8 + 2 * tg;
                float v0 = acc[mt][nt][half * 2 + 0];
                float v1 = acc[mt][nt][half * 2 + 1];
                if (applyRope) {
                    const int j = (n & (HD_ - 1)) >> 1;
                    float c_  = fc[s * HD_ + j * 2 + 0];
                    float sn_ = fc[s * HD_ + j * 2 + 1];
                    float r0 = v0 * c_  - v1 * sn_;
                    float i0 = v0 * sn_ + v1 * c_;
                    v0 = r0; v1 = i0;
                }
                *(float2*)(C + (size_t)m * D_ + n) = make_float2(v0, v1);
            }
        }
    }
}

// ---------------------------------------------------------------------------
// Tensor-core flash attention (causal, 3xBF16).
// Grid (S/64, NH, B), 128 threads = 4 warps; warp w owns q rows [w*16, w*16+16).
// kv-tile 32, double-buffered cp.async. qi reversed (heavy tiles first).
// Output written DIRECTLY as A-fragments for the output projection (validated R11).
// ---------------------------------------------------------------------------
#define ATT2_SMEM_BYTES (26752 * 4)

__global__ __launch_bounds__(128) void attention_mma(
    const unsigned* __restrict__ Qh_, const unsigned* __restrict__ Ql_,
    const unsigned* __restrict__ Kh_, const unsigned* __restrict__ Kl_,
    const unsigned* __restrict__ Vh_, const unsigned* __restrict__ Vl_,
    unsigned* __restrict__ Oh_, unsigned* __restrict__ Ol_)
{
    extern __shared__ unsigned smu[];
    unsigned* Qh = smu;              // [mt 4][kc 8][128]
    unsigned* Ql = smu + 4096;
    unsigned* KV = smu + 8192;       // 2 x { Kh 2048 | Kl 2048 | Vh 2048 | Vl 2048 }
    unsigned* PsHi = smu + 24576;    // [64][17]
    unsigned* PsLo = smu + 25664;

    const int tid  = threadIdx.x;
    const int warp = tid >> 5, lane = tid & 31;
    const int g = lane >> 2, tg = lane & 3;
    const int qi = (int)gridDim.x - 1 - (int)blockIdx.x;   // heavy tiles first
    const int bh = blockIdx.z * NH_ + blockIdx.y;
    const int Q0 = qi * 64;
    const float scale = 0.08838834764831845f;   // 1/sqrt(128)

    {
        size_t qbase = ((size_t)bh * 128 + qi * 4) * 1024;
        const uint4* srch = (const uint4*)(Qh_ + qbase);
        const uint4* srcl = (const uint4*)(Ql_ + qbase);
        for (int i = tid; i < 1024; i += 128) {
            ((uint4*)Qh)[i] = srch[i];
            ((uint4*)Ql)[i] = srcl[i];
        }
    }

    unsigned kvbase = (unsigned)__cvta_generic_to_shared(KV);

    auto copy_kv = [&](int kt, int b) {
        unsigned soff = kvbase + (unsigned)b * 8192u * 4u;
        size_t kbase = ((size_t)bh * 256 + kt * 4) * 512;
        for (int i = tid; i < 512; i += 128) {
            cp16(soff + i * 16u,               Kh_ + kbase + i * 4);
            cp16(soff + 2048u*4u + i * 16u,    Kl_ + kbase + i * 4);
        }
        for (int i = tid; i < 512; i += 128) {
            int tile = i >> 4, pos = i & 15;
            size_t vb = (((size_t)bh * 16 + (tile >> 1)) * 128 + (size_t)kt * 2 + (tile & 1)) * 64 + pos * 4;
            cp16(soff + 4096u*4u + i * 16u,    Vh_ + vb);
            cp16(soff + 6144u*4u + i * 16u,    Vl_ + vb);
        }
    };

    float m0 = -1e30f, m1 = -1e30f, l0 = 0.f, l1 = 0.f;
    float o[16][4];
    #pragma unroll
    for (int nt = 0; nt < 16; nt++)
        #pragma unroll
        for (int f = 0; f < 4; f++) o[nt][f] = 0.f;

    const int ktmax = 2 * qi + 2;
    copy_kv(0, 0);
    cp_commit();
    __syncthreads();

    const int prow0 = warp * 16 + g;
    const int prow1 = prow0 + 8;
    const int qrow0 = Q0 + prow0;

    for (int kt = 0; kt < ktmax; kt++) {
        if (kt + 1 < ktmax) copy_kv(kt + 1, (kt + 1) & 1);
        cp_commit();
        cp_wait1();
        __syncthreads();

        const unsigned* Kh_s = KV + (kt & 1) * 8192;
        const unsigned* Kl_s = Kh_s + 2048;
        const unsigned* Vh_s = Kh_s + 4096;
        const unsigned* Vl_s = Kh_s + 6144;

        float s[4][4];
        #pragma unroll
        for (int nt = 0; nt < 4; nt++)
            #pragma unroll
            for (int f = 0; f < 4; f++) s[nt][f] = 0.f;

        #pragma unroll
        for (int kc = 0; kc < 8; kc++) {
            uint4 ah = *(const uint4*)(Qh + (warp*8 + kc) * 128 + lane * 4);
            uint4 al = *(const uint4*)(Ql + (warp*8 + kc) * 128 + lane * 4);
            #pragma unroll
            for (int nt = 0; nt < 4; nt++) {
                uint2 kbh = *(const uint2*)(Kh_s + (nt*8 + kc) * 64 + lane * 2);
                uint2 kbl = *(const uint2*)(Kl_s + (nt*8 + kc) * 64 + lane * 2);
                mma_bf16(s[nt], (const unsigned*)&ah, (const unsigned*)&kbl);
                mma_bf16(s[nt], (const unsigned*)&al, (const unsigned*)&kbh);
                mma_bf16(s[nt], (const unsigned*)&ah, (const unsigned*)&kbh);
            }
        }

        const bool needMask = (kt >= 2 * qi);
        float mloc0 = -1e30f, mloc1 = -1e30f;
        #pragma unroll
        for (int nt = 0; nt < 4; nt++) {
            #pragma unroll
            for (int j = 0; j < 2; j++) {
                int col = kt*32 + nt*8 + 2*tg + j;
                float sv0 = s[nt][j]   * scale;
                float sv1 = s[nt][2+j] * scale;
                if (needMask) {
                    if (col > qrow0)     sv0 = -1e30f;
                    if (col > qrow0 + 8) sv1 = -1e30f;
                }
                s[nt][j] = sv0; s[nt][2+j] = sv1;
                mloc0 = fmaxf(mloc0, sv0);
                mloc1 = fmaxf(mloc1, sv1);
            }
        }
        mloc0 = fmaxf(mloc0, __shfl_xor_sync(0xffffffffu, mloc0, 1));
        mloc0 = fmaxf(mloc0, __shfl_xor_sync(0xffffffffu, mloc0, 2));
        mloc1 = fmaxf(mloc1, __shfl_xor_sync(0xffffffffu, mloc1, 1));
        mloc1 = fmaxf(mloc1, __shfl_xor_sync(0xffffffffu, mloc1, 2));

        float mn0 = fmaxf(m0, mloc0), mn1 = fmaxf(m1, mloc1);
        float corr0 = __expf(m0 - mn0), corr1 = __expf(m1 - mn1);
        float ls0 = 0.f, ls1 = 0.f;
        #pragma unroll
        for (int nt = 0; nt < 4; nt++) {
            #pragma unroll
            for (int j = 0; j < 2; j++) {
                float p0 = __expf(s[nt][j]   - mn0);
                float p1 = __expf(s[nt][2+j] - mn1);
                s[nt][j] = p0; s[nt][2+j] = p1;
                ls0 += p0; ls1 += p1;
            }
        }
        ls0 += __shfl_xor_sync(0xffffffffu, ls0, 1);
        ls0 += __shfl_xor_sync(0xffffffffu, ls0, 2);
        ls1 += __shfl_xor_sync(0xffffffffu, ls1, 1);
        ls1 += __shfl_xor_sync(0xffffffffu, ls1, 2);
        l0 = l0 * corr0 + ls0;  m0 = mn0;
        l1 = l1 * corr1 + ls1;  m1 = mn1;

        #pragma unroll
        for (int nt = 0; nt < 16; nt++) {
            o[nt][0] *= corr0; o[nt][1] *= corr0;
            o[nt][2] *= corr1; o[nt][3] *= corr1;
        }

        #pragma unroll
        for (int nt = 0; nt < 4; nt++) {
            unsigned hi, lo;
            split2(s[nt][0], s[nt][1], hi, lo);
            PsHi[prow0*17 + nt*4 + tg] = hi;
            PsLo[prow0*17 + nt*4 + tg] = lo;
            split2(s[nt][2], s[nt][3], hi, lo);
            PsHi[prow1*17 + nt*4 + tg] = hi;
            PsLo[prow1*17 + nt*4 + tg] = lo;
        }
        __syncwarp();

        #pragma unroll
        for (int kc = 0; kc < 2; kc++) {
            unsigned phi[4] = { PsHi[prow0*17 + kc*8 + tg],     PsHi[prow1*17 + kc*8 + tg],
                                PsHi[prow0*17 + kc*8 + 4 + tg], PsHi[prow1*17 + kc*8 + 4 + tg] };
            unsigned plo[4] = { PsLo[prow0*17 + kc*8 + tg],     PsLo[prow1*17 + kc*8 + tg],
                                PsLo[prow0*17 + kc*8 + 4 + tg], PsLo[prow1*17 + kc*8 + 4 + tg] };
            #pragma unroll
            for (int nt = 0; nt < 16; nt++) {
                uint2 vh = *(const uint2*)(Vh_s + (nt*2 + kc) * 64 + lane * 2);
                uint2 vl = *(const uint2*)(Vl_s + (nt*2 + kc) * 64 + lane * 2);
                mma_bf16(o[nt], phi, (const unsigned*)&vl);
                mma_bf16(o[nt], plo, (const unsigned*)&vh);
                mma_bf16(o[nt], phi, (const unsigned*)&vh);
            }
        }
        __syncthreads();
    }

    // ---- normalize + split + store directly as output-projection A-frags ----
    float inv0 = 1.0f / l0, inv1 = 1.0f / l1;
    const int b = bh >> 4, h = bh & 15;
    const int mtile = b * 128 + qi * 4 + warp;   // global 16-row tile index
    #pragma unroll
    for (int j = 0; j < 8; j++) {
        uint4 hi, lo;
        split2(o[2*j  ][0]*inv0, o[2*j  ][1]*inv0, hi.x, lo.x);
        split2(o[2*j  ][2]*inv1, o[2*j  ][3]*inv1, hi.y, lo.y);
        split2(o[2*j+1][0]*inv0, o[2*j+1][1]*inv0, hi.z, lo.z);
        split2(o[2*j+1][2]*inv1, o[2*j+1][3]*inv1, hi.w, lo.w);
        size_t base = ((size_t)mtile * KC_N + (h*8 + j)) * 128 + lane * 4;
        *(uint4*)(Oh_ + base) = hi;
        *(uint4*)(Ol_ + base) = lo;
    }
}

// ---------------------------------------------------------------------------
// Launch. Inputs: x, start_pos, freqs_cis, mask, wq, wk, wv, wo
// ---------------------------------------------------------------------------
extern "C" void kernel_launch(void* const* d_in, const int* in_sizes, int n_in,
                              void* d_out, int out_size) {
    (void)in_sizes; (void)n_in; (void)out_size;
    const float* x  = (const float*)d_in[0];
    const float* fc = (const float*)d_in[2];
    const float* w[4] = { (const float*)d_in[4], (const float*)d_in[5],
                          (const float*)d_in[6], (const float*)d_in[7] };
    float* out = (float*)d_out;

    float *q, *k, *v;
    unsigned *xah, *xal, *oah, *oal, *wbh, *wbl;
    unsigned *qfh, *qfl, *kfh, *kfl, *vfh, *vfl;
    cudaGetSymbolAddress((void**)&q,    g_q);
    cudaGetSymbolAddress((void**)&k,    g_k);
    cudaGetSymbolAddress((void**)&v,    g_v);
    cudaGetSymbolAddress((void**)&xah,  g_xah);
    cudaGetSymbolAddress((void**)&xal,  g_xal);
    cudaGetSymbolAddress((void**)&oah,  g_oah);
    cudaGetSymbolAddress((void**)&oal,  g_oal);
    cudaGetSymbolAddress((void**)&wbh,  g_wbh);
    cudaGetSymbolAddress((void**)&wbl,  g_wbl);
    cudaGetSymbolAddress((void**)&qfh,  g_qfh);
    cudaGetSymbolAddress((void**)&qfl,  g_qfl);
    cudaGetSymbolAddress((void**)&kfh,  g_kfh);
    cudaGetSymbolAddress((void**)&kfl,  g_kfl);
    cudaGetSymbolAddress((void**)&vfh,  g_vfh);
    cudaGetSymbolAddress((void**)&vfl,  g_vfl);

    cudaFuncSetAttribute(gemm_frag_rope,
                         cudaFuncAttributeMaxDynamicSharedMemorySize, GEMM_SMEM_BYTES);
    cudaFuncSetAttribute(attention_mma,
                         cudaFuncAttributeMaxDynamicSharedMemorySize, ATT2_SMEM_BYTES);

    // Pre-split operands (weights batched into one launch)
    split_a_kernel<<<dim3(M_/64, D_/32), 256>>>(x, xah, xal);
    split_b_kernel<<<dim3(D_/64, D_/32, 4), 256>>>(w[0], w[1], w[2], w[3], wbh, wbl);

    // Fused Q/K/V projections (z selects weight slab + output; rope on z=0,1)
    dim3 gemm_grid(M_/128, D_/128, 3);   // (32, 16, 3)
    gemm_frag_rope<<<gemm_grid, 256, GEMM_SMEM_BYTES>>>(xah, xal, wbh, wbl,
        q, k, v, fc, 0b011);

    // Split Q/K/V into attention fragment layouts
    dim3 sgrid(S_/64, HD_/32, B_*NH_);   // (32, 4, 32)
    split_q_frag<<<sgrid, 256>>>(q, qfh, qfl);
    split_k_frag<<<sgrid, 256>>>(k, kfh, kfl);
    split_v_frag<<<sgrid, 256>>>(v, vfh, vfl);

    // Tensor-core flash attention; writes output-projection A-frags directly
    dim3 att_grid(S_/64, NH_, B_);       // (32, 16, 2)
    attention_mma<<<att_grid, 128, ATT2_SMEM_BYTES>>>(qfh, qfl, kfh, kfl, vfh, vfl,
                                                      oah, oal);

    // Output projection (weight slab 3 selected via pointer offset, z=0)
    dim3 o_grid(M_/128, D_/128, 1);
    gemm_frag_rope<<<o_grid, 256, GEMM_SMEM_BYTES>>>(oah, oal,
        wbh + 3*B_FRAG_U32, wbl + 3*B_FRAG_U32, out, out, out, fc, 0);
}

// round 13
// speedup vs baseline: 1.0812x; 1.0104x over previous
#include <cuda_runtime.h>
#include <cuda_bf16.h>
#include <math.h>

// Problem constants
#define B_   2
#define S_   2048
#define D_   2048
#define NH_  16
#define HD_  128
#define M_   (B_*S_)          // 4096 total rows
#define KC_N (D_/16)          // 128 k16-chunks per row
#define NK_  (D_/32)          // 64 k-iterations of BK=32

// ---------------------------------------------------------------------------
// Scratch (static device globals — no runtime allocation allowed)
// ---------------------------------------------------------------------------
__device__ float g_q[(size_t)M_ * D_];
__device__ float g_k[(size_t)M_ * D_];
__device__ float g_v[(size_t)M_ * D_];

// Fragment-major pre-split bf16 operands (packed bf16x2 in u32)
#define A_FRAG_U32 ((size_t)(M_/16) * KC_N * 128)   // 4,194,304
#define B_FRAG_U32 ((size_t)(D_/8) * KC_N * 64)     // 2,097,152
__device__ unsigned g_xah[A_FRAG_U32], g_xal[A_FRAG_U32];
__device__ unsigned g_oah[A_FRAG_U32], g_oal[A_FRAG_U32];
__device__ unsigned g_wbh[4][B_FRAG_U32], g_wbl[4][B_FRAG_U32];

// Attention fragments, per (b,h):
// Q A-frag:   [bh 32][mt 128][kc 8][128]
// K B-frag:   [bh 32][nt 256][kc 8][64]
// V B-frag(T):[bh 32][ntd 16][kcs 128][64]
#define QF_U32 ((size_t)32 * 128 * 8 * 128)
#define KF_U32 ((size_t)32 * 256 * 8 * 64)
#define VF_U32 ((size_t)32 * 16 * 128 * 64)
__device__ unsigned g_qfh[QF_U32], g_qfl[QF_U32];
__device__ unsigned g_kfh[KF_U32], g_kfl[KF_U32];
__device__ unsigned g_vfh[VF_U32], g_vfl[VF_U32];

// ---------------------------------------------------------------------------
// bf16 helpers (3xBF16 = near-fp32 precision; drops only lo*lo ~ 2^-18)
// ---------------------------------------------------------------------------
__device__ __forceinline__ unsigned pack2(float x, float y) {
    __nv_bfloat162 t = __floats2bfloat162_rn(x, y);   // x -> low half
    return *reinterpret_cast<unsigned*>(&t);
}
__device__ __forceinline__ void split2(float x, float y, unsigned &hi, unsigned &lo) {
    float hx = __bfloat162float(__float2bfloat16_rn(x));
    float hy = __bfloat162float(__float2bfloat16_rn(y));
    hi = pack2(hx, hy);
    lo = pack2(x - hx, y - hy);
}

__device__ __forceinline__ void mma_bf16(float* c, const unsigned* a, const unsigned* b) {
    asm volatile(
        "mma.sync.aligned.m16n8k16.row.col.f32.bf16.bf16.f32 "
        "{%0,%1,%2,%3}, {%4,%5,%6,%7}, {%8,%9}, {%0,%1,%2,%3};"
        : "+f"(c[0]), "+f"(c[1]), "+f"(c[2]), "+f"(c[3])
        : "r"(a[0]), "r"(a[1]), "r"(a[2]), "r"(a[3]),
          "r"(b[0]), "r"(b[1]));
}

__device__ __forceinline__ void cp16(unsigned s, const void* g) {
    asm volatile("cp.async.cg.shared.global [%0], [%1], 16;\n" :: "r"(s), "l"(g));
}
__device__ __forceinline__ void cp_commit() {
    asm volatile("cp.async.commit_group;\n" ::: "memory");
}
__device__ __forceinline__ void cp_wait1() {
    asm volatile("cp.async.wait_group 1;\n" ::: "memory");
}

// ---------------------------------------------------------------------------
// Split kernels (row-major fp32 -> fragment-major packed bf16 hi/lo)
// ---------------------------------------------------------------------------
// A split (x). grid (R/64, 64), 256 threads.
__global__ __launch_bounds__(256) void split_a_kernel(
    const float* __restrict__ src, unsigned* __restrict__ dhi, unsigned* __restrict__ dlo)
{
    __shared__ float S[64][33];
    const int tid = threadIdx.x;
    const int row0 = blockIdx.x * 64;
    const int col0 = blockIdx.y * 32;
    #pragma unroll
    for (int i = 0; i < 8; i++) {
        int lin = tid + i * 256;
        int r = lin >> 5, c = lin & 31;
        S[r][c] = src[(size_t)(row0 + r) * D_ + col0 + c];
    }
    __syncthreads();
    const int warp = tid >> 5, lane = tid & 31;
    const int g = lane >> 2, tg = lane & 3;
    const int mt = warp >> 1, kc = warp & 1;
    const int m0 = mt * 16, k0 = kc * 16;
    uint4 hi, lo;
    split2(S[m0 + g    ][k0 + 2*tg    ], S[m0 + g    ][k0 + 2*tg + 1], hi.x, lo.x);
    split2(S[m0 + 8 + g][k0 + 2*tg    ], S[m0 + 8 + g][k0 + 2*tg + 1], hi.y, lo.y);
    split2(S[m0 + g    ][k0 + 2*tg + 8], S[m0 + g    ][k0 + 2*tg + 9], hi.z, lo.z);
    split2(S[m0 + 8 + g][k0 + 2*tg + 8], S[m0 + 8 + g][k0 + 2*tg + 9], hi.w, lo.w);
    size_t base = ((size_t)(blockIdx.x*4 + mt) * KC_N + (blockIdx.y*2 + kc)) * 128 + lane * 4;
    *(uint4*)(dhi + base) = hi;
    *(uint4*)(dlo + base) = lo;
}

// B split (weights, batched over 4 slabs via blockIdx.z). grid (32, 64, 4).
__global__ __launch_bounds__(256) void split_b_kernel(
    const float* __restrict__ w0, const float* __restrict__ w1,
    const float* __restrict__ w2, const float* __restrict__ w3,
    unsigned* __restrict__ dhi_base, unsigned* __restrict__ dlo_base)
{
    __shared__ float S[64][33];
    const int tid = threadIdx.x;
    const int z = blockIdx.z;
    const float* src = (z == 0) ? w0 : (z == 1) ? w1 : (z == 2) ? w2 : w3;
    unsigned* dhi = dhi_base + (size_t)z * B_FRAG_U32;
    unsigned* dlo = dlo_base + (size_t)z * B_FRAG_U32;
    const int row0 = blockIdx.x * 64;
    const int col0 = blockIdx.y * 32;
    #pragma unroll
    for (int i = 0; i < 8; i++) {
        int lin = tid + i * 256;
        int r = lin >> 5, c = lin & 31;
        S[r][c] = src[(size_t)(row0 + r) * D_ + col0 + c];
    }
    __syncthreads();
    const int warp = tid >> 5, lane = tid & 31;
    const int g = lane >> 2, tg = lane & 3;
    #pragma unroll
    for (int it = 0; it < 2; it++) {
        int t = warp * 2 + it;
        int nt = t >> 1, kc = t & 1;
        int n0 = nt * 8, k0 = kc * 16;
        uint2 hi, lo;
        split2(S[n0 + g][k0 + 2*tg    ], S[n0 + g][k0 + 2*tg + 1], hi.x, lo.x);
        split2(S[n0 + g][k0 + 2*tg + 8], S[n0 + g][k0 + 2*tg + 9], hi.y, lo.y);
        size_t base = ((size_t)(blockIdx.x*8 + nt) * KC_N + (blockIdx.y*2 + kc)) * 64 + lane * 2;
        *(uint2*)(dhi + base) = hi;
        *(uint2*)(dlo + base) = lo;
    }
}

// Q split per (b,h). grid (32, 4, 32).
__global__ __launch_bounds__(256) void split_q_frag(
    const float* __restrict__ src, unsigned* __restrict__ dhi, unsigned* __restrict__ dlo)
{
    __shared__ float S[64][33];
    const int tid = threadIdx.x;
    const int bh = blockIdx.z;
    const int b = bh >> 4, h = bh & 15;
    const int row0 = b * S_ + blockIdx.x * 64;
    const int col0 = h * HD_ + blockIdx.y * 32;
    #pragma unroll
    for (int i = 0; i < 8; i++) {
        int lin = tid + i * 256;
        int r = lin >> 5, c = lin & 31;
        S[r][c] = src[(size_t)(row0 + r) * D_ + col0 + c];
    }
    __syncthreads();
    const int warp = tid >> 5, lane = tid & 31;
    const int g = lane >> 2, tg = lane & 3;
    const int mt = warp >> 1, kc = warp & 1;
    const int m0 = mt * 16, k0 = kc * 16;
    uint4 hi, lo;
    split2(S[m0 + g    ][k0 + 2*tg    ], S[m0 + g    ][k0 + 2*tg + 1], hi.x, lo.x);
    split2(S[m0 + 8 + g][k0 + 2*tg    ], S[m0 + 8 + g][k0 + 2*tg + 1], hi.y, lo.y);
    split2(S[m0 + g    ][k0 + 2*tg + 8], S[m0 + g    ][k0 + 2*tg + 9], hi.z, lo.z);
    split2(S[m0 + 8 + g][k0 + 2*tg + 8], S[m0 + 8 + g][k0 + 2*tg + 9], hi.w, lo.w);
    size_t base = (((size_t)bh*128 + blockIdx.x*4 + mt) * 8 + (blockIdx.y*2 + kc)) * 128 + lane * 4;
    *(uint4*)(dhi + base) = hi;
    *(uint4*)(dlo + base) = lo;
}

// K split per (b,h). grid (32, 4, 32).
__global__ __launch_bounds__(256) void split_k_frag(
    const float* __restrict__ src, unsigned* __restrict__ dhi, unsigned* __restrict__ dlo)
{
    __shared__ float S[64][33];
    const int tid = threadIdx.x;
    const int bh = blockIdx.z;
    const int b = bh >> 4, h = bh & 15;
    const int row0 = b * S_ + blockIdx.x * 64;
    const int col0 = h * HD_ + blockIdx.y * 32;
    #pragma unroll
    for (int i = 0; i < 8; i++) {
        int lin = tid + i * 256;
        int r = lin >> 5, c = lin & 31;
        S[r][c] = src[(size_t)(row0 + r) * D_ + col0 + c];
    }
    __syncthreads();
    const int warp = tid >> 5, lane = tid & 31;
    const int g = lane >> 2, tg = lane & 3;
    #pragma unroll
    for (int it = 0; it < 2; it++) {
        int t = warp * 2 + it;
        int nt = t >> 1, kc = t & 1;
        int n0 = nt * 8, k0 = kc * 16;
        uint2 hi, lo;
        split2(S[n0 + g][k0 + 2*tg    ], S[n0 + g][k0 + 2*tg + 1], hi.x, lo.x);
        split2(S[n0 + g][k0 + 2*tg + 8], S[n0 + g][k0 + 2*tg + 9], hi.y, lo.y);
        size_t base = (((size_t)bh*256 + blockIdx.x*8 + nt) * 8 + (blockIdx.y*2 + kc)) * 64 + lane * 2;
        *(uint2*)(dhi + base) = hi;
        *(uint2*)(dlo + base) = lo;
    }
}

// V transposed split: B-frag with n = headdim, k = seqpos. grid (32, 4, 32).
__global__ __launch_bounds__(256) void split_v_frag(
    const float* __restrict__ src, unsigned* __restrict__ dhi, unsigned* __restrict__ dlo)
{
    __shared__ float S[64][33];
    const int tid = threadIdx.x;
    const int bh = blockIdx.z;
    const int b = bh >> 4, h = bh & 15;
    const int row0 = b * S_ + blockIdx.x * 64;   // seq
    const int col0 = h * HD_ + blockIdx.y * 32;  // headdim
    #pragma unroll
    for (int i = 0; i < 8; i++) {
        int lin = tid + i * 256;
        int r = lin >> 5, c = lin & 31;
        S[r][c] = src[(size_t)(row0 + r) * D_ + col0 + c];
    }
    __syncthreads();
    const int warp = tid >> 5, lane = tid & 31;
    const int g = lane >> 2, tg = lane & 3;
    #pragma unroll
    for (int it = 0; it < 2; it++) {
        int t = warp * 2 + it;
        int ntl = t & 3, ks = t >> 2;
        int s0 = ks * 16, d0 = ntl * 8;
        uint2 hi, lo;
        split2(S[s0 + 2*tg    ][d0 + g], S[s0 + 2*tg + 1][d0 + g], hi.x, lo.x);
        split2(S[s0 + 2*tg + 8][d0 + g], S[s0 + 2*tg + 9][d0 + g], hi.y, lo.y);
        size_t base = (((size_t)bh*16 + blockIdx.y*4 + ntl) * 128 + (blockIdx.x*4 + ks)) * 64 + lane * 2;
        *(uint2*)(dhi + base) = hi;
        *(uint2*)(dlo + base) = lo;
    }
}

// ---------------------------------------------------------------------------
// GEMM (TN) on pre-split bf16 fragments, 3xBF16 (R10 version, verbatim).
// Block 128x128, BK=32 (2 k-chunks), 256 threads = 8 warps (2m x 4n).
// Fused over blockIdx.z: selects weight slab + output + rope flag.
// ---------------------------------------------------------------------------
#define GEMM_SMEM_BYTES (2 * 8192 * 4)   // 65536

__global__ __launch_bounds__(256) void gemm_frag_rope(
    const unsigned* __restrict__ Ahi, const unsigned* __restrict__ Alo,
    const unsigned* __restrict__ Bh_base, const unsigned* __restrict__ Bl_base,
    float* __restrict__ out0, float* __restrict__ out1, float* __restrict__ out2,
    const float* __restrict__ fc, int ropeMask)
{
    extern __shared__ unsigned smu[];
    const int z = blockIdx.z;
    const unsigned* Bhi = Bh_base + (size_t)z * B_FRAG_U32;
    const unsigned* Blo = Bl_base + (size_t)z * B_FRAG_U32;
    float* C = (z == 0) ? out0 : ((z == 1) ? out1 : out2);
    const int applyRope = (ropeMask >> z) & 1;

    const int tid  = threadIdx.x;
    const int warp = tid >> 5, lane = tid & 31;
    const int wm = warp >> 2, wn = warp & 3;
    const int g  = lane >> 2, tg = lane & 3;
    const int MT0 = blockIdx.x * 8;    // 8 mtiles per block
    const int NT0 = blockIdx.y * 16;   // 16 ntiles per block

    float acc[4][4][4];
    #pragma unroll
    for (int i = 0; i < 4; i++)
        #pragma unroll
        for (int j = 0; j < 4; j++)
            #pragma unroll
            for (int f = 0; f < 4; f++) acc[i][j][f] = 0.f;

    unsigned sbase = (unsigned)__cvta_generic_to_shared(smu);

    auto copy_tile = [&](int kt, int b) {
        unsigned soff = sbase + b * 8192u * 4u;
        #pragma unroll
        for (int i = 0; i < 2; i++) {
            int id = tid + i * 256;
            int tile = id >> 5, pos = id & 31;
            size_t gb = ((size_t)(MT0 + (tile >> 1)) * KC_N + kt*2 + (tile & 1)) * 128 + pos * 4;
            unsigned so = soff + (unsigned)(tile * 128 + pos * 4) * 4u;
            cp16(so,               Ahi + gb);
            cp16(so + 2048u * 4u,  Alo + gb);
        }
        #pragma unroll
        for (int i = 0; i < 2; i++) {
            int id = tid + i * 256;
            int tile = id >> 4, pos = id & 15;
            size_t gb = ((size_t)(NT0 + (tile >> 1)) * KC_N + kt*2 + (tile & 1)) * 64 + pos * 4;
            unsigned so = soff + (unsigned)(4096 + tile * 64 + pos * 4) * 4u;
            cp16(so,               Bhi + gb);
            cp16(so + 2048u * 4u,  Blo + gb);
        }
    };

    copy_tile(0, 0);
    cp_commit();

    for (int kt = 0; kt < NK_; kt++) {
        if (kt + 1 < NK_) copy_tile(kt + 1, (kt + 1) & 1);
        cp_commit();
        cp_wait1();
        __syncthreads();

        const unsigned* buf = smu + (kt & 1) * 8192;
        const uint4* As_h = (const uint4*)(buf);
        const uint4* As_l = (const uint4*)(buf + 2048);
        const uint2* Bs_h = (const uint2*)(buf + 4096);
        const uint2* Bs_l = (const uint2*)(buf + 6144);

        #pragma unroll
        for (int kc = 0; kc < 2; kc++) {
            uint4 ah[4], al[4];
            #pragma unroll
            for (int mt = 0; mt < 4; mt++) {
                int idx = ((wm*4 + mt)*2 + kc) * 32 + lane;
                ah[mt] = As_h[idx];
                al[mt] = As_l[idx];
            }
            uint2 bh[4], bl[4];
            #pragma unroll
            for (int nt = 0; nt < 4; nt++) {
                int idx = ((wn*4 + nt)*2 + kc) * 32 + lane;
                bh[nt] = Bs_h[idx];
                bl[nt] = Bs_l[idx];
            }
            #pragma unroll
            for (int mt = 0; mt < 4; mt++)
                #pragma unroll
                for (int nt = 0; nt < 4; nt++) {
                    mma_bf16(acc[mt][nt], (const unsigned*)&ah[mt], (const unsigned*)&bl[nt]);
                    mma_bf16(acc[mt][nt], (const unsigned*)&al[mt], (const unsigned*)&bh[nt]);
                    mma_bf16(acc[mt][nt], (const unsigned*)&ah[mt], (const unsigned*)&bh[nt]);
                }
        }
        __syncthreads();
    }

    // Epilogue: c0,c1=(row,2tg),(row,2tg+1); c2,c3=row+8. RoPE pair = (2tg,2tg+1).
    const int bm = blockIdx.x * 128, bn = blockIdx.y * 128;
    #pragma unroll
    for (int mt = 0; mt < 4; mt++) {
        #pragma unroll
        for (int half = 0; half < 2; half++) {
            const int m = bm + wm * 64 + mt * 16 + g + half * 8;
            const int s = m & (S_ - 1);
            #pragma unroll
            for (int nt = 0; nt < 4; nt++) {
                const int n = bn + wn * 32 + nt * 8 + 2 * tg;
                float v0 = acc[mt][nt][half * 2 + 0];
                float v1 = acc[mt][nt][half * 2 + 1];
                if (applyRope) {
                    const int j = (n & (HD_ - 1)) >> 1;
                    float c_  = fc[s * HD_ + j * 2 + 0];
                    float sn_ = fc[s * HD_ + j * 2 + 1];
                    float r0 = v0 * c_  - v1 * sn_;
                    float i0 = v0 * sn_ + v1 * c_;
                    v0 = r0; v1 = i0;
                }
                *(float2*)(C + (size_t)m * D_ + n) = make_float2(v0, v1);
            }
        }
    }
}

// ---------------------------------------------------------------------------
// Tensor-core flash attention (causal, 3xBF16).
// Grid (S/64, NH, B), 128 threads = 4 warps; warp w owns q rows [w*16, w*16+16).
// kv-tile 32, double-buffered cp.async. qi reversed (heavy tiles first).
// P fragments are THREAD-LOCAL (QK^T C-frag == PV A-frag) — no smem staging.
// Output written directly as A-fragments for the output projection.
// smem (u32): Qh[0,4096) Ql[4096,8192) KV 2x8192 [8192,24576)
// ---------------------------------------------------------------------------
#define ATT2_SMEM_BYTES (24576 * 4)

__global__ __launch_bounds__(128) void attention_mma(
    const unsigned* __restrict__ Qh_, const unsigned* __restrict__ Ql_,
    const unsigned* __restrict__ Kh_, const unsigned* __restrict__ Kl_,
    const unsigned* __restrict__ Vh_, const unsigned* __restrict__ Vl_,
    unsigned* __restrict__ Oh_, unsigned* __restrict__ Ol_)
{
    extern __shared__ unsigned smu[];
    unsigned* Qh = smu;              // [mt 4][kc 8][128]
    unsigned* Ql = smu + 4096;
    unsigned* KV = smu + 8192;       // 2 x { Kh 2048 | Kl 2048 | Vh 2048 | Vl 2048 }

    const int tid  = threadIdx.x;
    const int warp = tid >> 5, lane = tid & 31;
    const int g = lane >> 2, tg = lane & 3;
    const int qi = (int)gridDim.x - 1 - (int)blockIdx.x;   // heavy tiles first
    const int bh = blockIdx.z * NH_ + blockIdx.y;
    const int Q0 = qi * 64;
    const float scale = 0.08838834764831845f;   // 1/sqrt(128)

    {
        size_t qbase = ((size_t)bh * 128 + qi * 4) * 1024;
        const uint4* srch = (const uint4*)(Qh_ + qbase);
        const uint4* srcl = (const uint4*)(Ql_ + qbase);
        for (int i = tid; i < 1024; i += 128) {
            ((uint4*)Qh)[i] = srch[i];
            ((uint4*)Ql)[i] = srcl[i];
        }
    }

    unsigned kvbase = (unsigned)__cvta_generic_to_shared(KV);

    auto copy_kv = [&](int kt, int b) {
        unsigned soff = kvbase + (unsigned)b * 8192u * 4u;
        size_t kbase = ((size_t)bh * 256 + kt * 4) * 512;
        for (int i = tid; i < 512; i += 128) {
            cp16(soff + i * 16u,               Kh_ + kbase + i * 4);
            cp16(soff + 2048u*4u + i * 16u,    Kl_ + kbase + i * 4);
        }
        for (int i = tid; i < 512; i += 128) {
            int tile = i >> 4, pos = i & 15;
            size_t vb = (((size_t)bh * 16 + (tile >> 1)) * 128 + (size_t)kt * 2 + (tile & 1)) * 64 + pos * 4;
            cp16(soff + 4096u*4u + i * 16u,    Vh_ + vb);
            cp16(soff + 6144u*4u + i * 16u,    Vl_ + vb);
        }
    };

    float m0 = -1e30f, m1 = -1e30f, l0 = 0.f, l1 = 0.f;
    float o[16][4];
    #pragma unroll
    for (int nt = 0; nt < 16; nt++)
        #pragma unroll
        for (int f = 0; f < 4; f++) o[nt][f] = 0.f;

    const int ktmax = 2 * qi + 2;
    copy_kv(0, 0);
    cp_commit();
    __syncthreads();

    const int prow0 = warp * 16 + g;
    const int qrow0 = Q0 + prow0;

    for (int kt = 0; kt < ktmax; kt++) {
        if (kt + 1 < ktmax) copy_kv(kt + 1, (kt + 1) & 1);
        cp_commit();
        cp_wait1();
        __syncthreads();

        const unsigned* Kh_s = KV + (kt & 1) * 8192;
        const unsigned* Kl_s = Kh_s + 2048;
        const unsigned* Vh_s = Kh_s + 4096;
        const unsigned* Vl_s = Kh_s + 6144;

        float s[4][4];
        #pragma unroll
        for (int nt = 0; nt < 4; nt++)
            #pragma unroll
            for (int f = 0; f < 4; f++) s[nt][f] = 0.f;

        #pragma unroll
        for (int kc = 0; kc < 8; kc++) {
            uint4 ah = *(const uint4*)(Qh + (warp*8 + kc) * 128 + lane * 4);
            uint4 al = *(const uint4*)(Ql + (warp*8 + kc) * 128 + lane * 4);
            #pragma unroll
            for (int nt = 0; nt < 4; nt++) {
                uint2 kbh = *(const uint2*)(Kh_s + (nt*8 + kc) * 64 + lane * 2);
                uint2 kbl = *(const uint2*)(Kl_s + (nt*8 + kc) * 64 + lane * 2);
                mma_bf16(s[nt], (const unsigned*)&ah, (const unsigned*)&kbl);
                mma_bf16(s[nt], (const unsigned*)&al, (const unsigned*)&kbh);
                mma_bf16(s[nt], (const unsigned*)&ah, (const unsigned*)&kbh);
            }
        }

        const bool needMask = (kt >= 2 * qi);
        float mloc0 = -1e30f, mloc1 = -1e30f;
        #pragma unroll
        for (int nt = 0; nt < 4; nt++) {
            #pragma unroll
            for (int j = 0; j < 2; j++) {
                int col = kt*32 + nt*8 + 2*tg + j;
                float sv0 = s[nt][j]   * scale;
                float sv1 = s[nt][2+j] * scale;
                if (needMask) {
                    if (col > qrow0)     sv0 = -1e30f;
                    if (col > qrow0 + 8) sv1 = -1e30f;
                }
                s[nt][j] = sv0; s[nt][2+j] = sv1;
                mloc0 = fmaxf(mloc0, sv0);
                mloc1 = fmaxf(mloc1, sv1);
            }
        }
        mloc0 = fmaxf(mloc0, __shfl_xor_sync(0xffffffffu, mloc0, 1));
        mloc0 = fmaxf(mloc0, __shfl_xor_sync(0xffffffffu, mloc0, 2));
        mloc1 = fmaxf(mloc1, __shfl_xor_sync(0xffffffffu, mloc1, 1));
        mloc1 = fmaxf(mloc1, __shfl_xor_sync(0xffffffffu, mloc1, 2));

        float mn0 = fmaxf(m0, mloc0), mn1 = fmaxf(m1, mloc1);
        float corr0 = __expf(m0 - mn0), corr1 = __expf(m1 - mn1);
        float ls0 = 0.f, ls1 = 0.f;
        #pragma unroll
        for (int nt = 0; nt < 4; nt++) {
            #pragma unroll
            for (int j = 0; j < 2; j++) {
                float p0 = __expf(s[nt][j]   - mn0);
                float p1 = __expf(s[nt][2+j] - mn1);
                s[nt][j] = p0; s[nt][2+j] = p1;
                ls0 += p0; ls1 += p1;
            }
        }
        ls0 += __shfl_xor_sync(0xffffffffu, ls0, 1);
        ls0 += __shfl_xor_sync(0xffffffffu, ls0, 2);
        ls1 += __shfl_xor_sync(0xffffffffu, ls1, 1);
        ls1 += __shfl_xor_sync(0xffffffffu, ls1, 2);
        l0 = l0 * corr0 + ls0;  m0 = mn0;
        l1 = l1 * corr1 + ls1;  m1 = mn1;

        #pragma unroll
        for (int nt = 0; nt < 16; nt++) {
            o[nt][0] *= corr0; o[nt][1] *= corr0;
            o[nt][2] *= corr1; o[nt][3] *= corr1;
        }

        // ---- P fragments are thread-local: C-frag(QK) == A-frag(PV) ----
        // a0 = P[g][kp*16+2tg..+1]   = s[2kp][0..1]
        // a1 = P[g+8][kp*16+2tg..+1] = s[2kp][2..3]
        // a2 = P[g][kp*16+8+2tg..+1] = s[2kp+1][0..1]
        // a3 = P[g+8][...]           = s[2kp+1][2..3]
        #pragma unroll
        for (int kp = 0; kp < 2; kp++) {
            unsigned phi[4], plo[4];
            split2(s[2*kp  ][0], s[2*kp  ][1], phi[0], plo[0]);
            split2(s[2*kp  ][2], s[2*kp  ][3], phi[1], plo[1]);
            split2(s[2*kp+1][0], s[2*kp+1][1], phi[2], plo[2]);
            split2(s[2*kp+1][2], s[2*kp+1][3], phi[3], plo[3]);
            #pragma unroll
            for (int nt = 0; nt < 16; nt++) {
                uint2 vh = *(const uint2*)(Vh_s + (nt*2 + kp) * 64 + lane * 2);
                uint2 vl = *(const uint2*)(Vl_s + (nt*2 + kp) * 64 + lane * 2);
                mma_bf16(o[nt], phi, (const unsigned*)&vl);
                mma_bf16(o[nt], plo, (const unsigned*)&vh);
                mma_bf16(o[nt], phi, (const unsigned*)&vh);
            }
        }
        __syncthreads();
    }

    // ---- normalize + split + store directly as output-projection A-frags ----
    float inv0 = 1.0f / l0, inv1 = 1.0f / l1;
    const int b = bh >> 4, h = bh & 15;
    const int mtile = b * 128 + qi * 4 + warp;   // global 16-row tile index
    #pragma unroll
    for (int j = 0; j < 8; j++) {
        uint4 hi, lo;
        split2(o[2*j  ][0]*inv0, o[2*j  ][1]*inv0, hi.x, lo.x);
        split2(o[2*j  ][2]*inv1, o[2*j  ][3]*inv1, hi.y, lo.y);
        split2(o[2*j+1][0]*inv0, o[2*j+1][1]*inv0, hi.z, lo.z);
        split2(o[2*j+1][2]*inv1, o[2*j+1][3]*inv1, hi.w, lo.w);
        size_t base = ((size_t)mtile * KC_N + (h*8 + j)) * 128 + lane * 4;
        *(uint4*)(Oh_ + base) = hi;
        *(uint4*)(Ol_ + base) = lo;
    }
}

// ---------------------------------------------------------------------------
// Launch. Inputs: x, start_pos, freqs_cis, mask, wq, wk, wv, wo
// ---------------------------------------------------------------------------
extern "C" void kernel_launch(void* const* d_in, const int* in_sizes, int n_in,
                              void* d_out, int out_size) {
    (void)in_sizes; (void)n_in; (void)out_size;
    const float* x  = (const float*)d_in[0];
    const float* fc = (const float*)d_in[2];
    const float* w[4] = { (const float*)d_in[4], (const float*)d_in[5],
                          (const float*)d_in[6], (const float*)d_in[7] };
    float* out = (float*)d_out;

    float *q, *k, *v;
    unsigned *xah, *xal, *oah, *oal, *wbh, *wbl;
    unsigned *qfh, *qfl, *kfh, *kfl, *vfh, *vfl;
    cudaGetSymbolAddress((void**)&q,    g_q);
    cudaGetSymbolAddress((void**)&k,    g_k);
    cudaGetSymbolAddress((void**)&v,    g_v);
    cudaGetSymbolAddress((void**)&xah,  g_xah);
    cudaGetSymbolAddress((void**)&xal,  g_xal);
    cudaGetSymbolAddress((void**)&oah,  g_oah);
    cudaGetSymbolAddress((void**)&oal,  g_oal);
    cudaGetSymbolAddress((void**)&wbh,  g_wbh);
    cudaGetSymbolAddress((void**)&wbl,  g_wbl);
    cudaGetSymbolAddress((void**)&qfh,  g_qfh);
    cudaGetSymbolAddress((void**)&qfl,  g_qfl);
    cudaGetSymbolAddress((void**)&kfh,  g_kfh);
    cudaGetSymbolAddress((void**)&kfl,  g_kfl);
    cudaGetSymbolAddress((void**)&vfh,  g_vfh);
    cudaGetSymbolAddress((void**)&vfl,  g_vfl);

    cudaFuncSetAttribute(gemm_frag_rope,
                         cudaFuncAttributeMaxDynamicSharedMemorySize, GEMM_SMEM_BYTES);
    cudaFuncSetAttribute(attention_mma,
                         cudaFuncAttributeMaxDynamicSharedMemorySize, ATT2_SMEM_BYTES);

    // Pre-split operands (weights batched into one launch)
    split_a_kernel<<<dim3(M_/64, D_/32), 256>>>(x, xah, xal);
    split_b_kernel<<<dim3(D_/64, D_/32, 4), 256>>>(w[0], w[1], w[2], w[3], wbh, wbl);

    // Fused Q/K/V projections (z selects weight slab + output; rope on z=0,1)
    dim3 gemm_grid(M_/128, D_/128, 3);   // (32, 16, 3)
    gemm_frag_rope<<<gemm_grid, 256, GEMM_SMEM_BYTES>>>(xah, xal, wbh, wbl,
        q, k, v, fc, 0b011);

    // Split Q/K/V into attention fragment layouts
    dim3 sgrid(S_/64, HD_/32, B_*NH_);   // (32, 4, 32)
    split_q_frag<<<sgrid, 256>>>(q, qfh, qfl);
    split_k_frag<<<sgrid, 256>>>(k, kfh, kfl);
    split_v_frag<<<sgrid, 256>>>(v, vfh, vfl);

    // Tensor-core flash attention; writes output-projection A-frags directly
    dim3 att_grid(S_/64, NH_, B_);       // (32, 16, 2)
    attention_mma<<<att_grid, 128, ATT2_SMEM_BYTES>>>(qfh, qfl, kfh, kfl, vfh, vfl,
                                                      oah, oal);

    // Output projection (weight slab 3 selected via pointer offset, z=0)
    dim3 o_grid(M_/128, D_/128, 1);
    gemm_frag_rope<<<o_grid, 256, GEMM_SMEM_BYTES>>>(oah, oal,
        wbh + 3*B_FRAG_U32, wbl + 3*B_FRAG_U32, out, out, out, fc, 0);
}